// round 11
// baseline (speedup 1.0000x reference)
#include <cuda_runtime.h>
#include <math.h>

// Problem constants (shapes fixed by the dataset)
#define BATCH 8
#define R 300
#define C 21
#define NC 20           // foreground classes
#define KPAD 21         // output pad size == num_classes
#define RW 10           // ceil(300/32) keep-bitmask words
#define NMS_T 0.3f
#define NT 1024         // threads per block (2 independent halves of 512)
#define HT 512          // threads per half
#define NW 16           // warps per half
#define NPAIR (NC / 2)  // class pairs per image = blocks per image

// Cross-block intermediates (allocation-free rule: device globals)
__device__ float4   g_sb[BATCH * NC * R];      // sorted+clipped boxes per (b,class)
__device__ unsigned g_keep[BATCH * NC * RW];   // keep bitmask per (b,class)
__device__ int      g_ctr[BATCH];              // arrival counters (self-resetting)

struct Smem {
    float4  box[2][R];             // decoded boxes by original index
    float4  sb[2][R];              // boxes in sorted order (valid prefix)
    unsigned long long ckeys[2][R];// compacted valid keys, index order
    float   area[2][R];            // areas in sorted order
    unsigned mask[2][R][RW];       // suppression bitmask (valid prefix)
    int     rnk[2][R];             // rank accumulation
    int warpcnt[2][NW];
    int warpoff[2][NW];
    int sV[2];
    int sOld[2];
    unsigned slive[2][RW], skept[2][RW], sknew[2][RW];
    unsigned skw[NC][RW];          // tail selection scratch
    int sexcl[32];
};

// Per-half barrier: ids 1 and 2 (0 is reserved for __syncthreads).
__device__ __forceinline__ void bar_half(int half) {
    asm volatile("bar.sync %0, %1;" :: "r"(half + 1), "r"(HT) : "memory");
}

__global__ __launch_bounds__(NT, 1) void fused_nms_kernel(
    const float* __restrict__ cls_prob,   // [B,R,C]
    const float* __restrict__ rois,       // [B,R,5]
    const float* __restrict__ bbox_pred,  // [B,R,4C]
    const float* __restrict__ im_info,    // [B,3]
    const float* __restrict__ thr_arr,    // [C]
    float* __restrict__ out, int out_size)
{
    extern __shared__ __align__(16) unsigned char smem_raw[];
    Smem& S = *reinterpret_cast<Smem*>(smem_raw);

    const int blk  = blockIdx.x;
    const int b    = blk / NPAIR;
    const int t    = threadIdx.x;
    const int half = t >> 9;                 // 0 or 1: which class of the pair
    const int tl   = t & (HT - 1);           // thread id within half
    const int lane = t & 31;
    const int wl   = tl >> 5;                // warp id within half (0..15)
    const int cc   = (blk % NPAIR) * 2 + half;   // 0..19
    const int c    = cc + 1;                 // class id 1..20

    const float thr = thr_arr[c];
    const float H1 = im_info[b * 3 + 0] - 1.0f;
    const float W1 = im_info[b * 3 + 1] - 1.0f;

    // ---- decode + clip + key (one row per thread; arithmetic identical to R1) ----
    int valid = 0;
    unsigned long long key = ~0ULL;
    const int r = tl;
    if (r < R) {
        const float* rp = rois + (size_t)(b * R + r) * 5;
        float x1 = rp[1], y1 = rp[2], x2 = rp[3], y2 = rp[4];
        float w  = x2 - x1 + 1.0f;
        float h  = y2 - y1 + 1.0f;
        float cx = x1 + 0.5f * w;
        float cy = y1 + 0.5f * h;

        // 16B-aligned: byte offset = 336*(b*R+r) + 16*c
        const float4 d4 = *reinterpret_cast<const float4*>(
            bbox_pred + (size_t)(b * R + r) * (4 * C) + 4 * c);
        float d0 = d4.x * 0.1f;
        float d1 = d4.y * 0.1f;
        float d2 = d4.z * 0.2f;
        float d3 = d4.w * 0.2f;

        float pcx = d0 * w + cx;
        float pcy = d1 * h + cy;
        float pw  = expf(d2) * w;
        float ph  = expf(d3) * h;

        float bx1 = fminf(fmaxf(pcx - 0.5f * pw, 0.0f), W1);
        float by1 = fminf(fmaxf(pcy - 0.5f * ph, 0.0f), H1);
        float bx2 = fminf(fmaxf(pcx + 0.5f * pw, 0.0f), W1);
        float by2 = fminf(fmaxf(pcy + 0.5f * ph, 0.0f), H1);
        S.box[half][r] = make_float4(bx1, by1, bx2, by2);

        float s = cls_prob[(size_t)(b * R + r) * C + c];
        valid = (s > thr) ? 1 : 0;

        // monotone float->uint, inverted => ascending sort == descending score,
        // low 32 bits = original index (stable tie-break).
        unsigned u = __float_as_uint(s);
        unsigned m = (u & 0x80000000u) ? ~u : (u | 0x80000000u);
        key = (((unsigned long long)(~m)) << 32) | (unsigned)r;
    }

    // ---- stable compaction of valid rows per half (index order preserved) ----
    unsigned bal = __ballot_sync(0xffffffffu, valid);
    if (lane == 0) S.warpcnt[half][wl] = __popc(bal);
    bar_half(half);
    if (tl < NW) {
        int v = S.warpcnt[half][tl];
        int incl = v;
        #pragma unroll
        for (int off = 1; off < NW; off <<= 1) {
            int n = __shfl_up_sync(0x0000ffffu, incl, off);
            if (tl >= off) incl += n;
        }
        S.warpoff[half][tl] = incl - v;
        if (tl == NW - 1) S.sV[half] = incl;
    }
    bar_half(half);
    const int V  = S.sV[half];
    const int VW = (V + 31) >> 5;

    if (valid) {
        int pos = S.warpoff[half][wl] + __popc(bal & ((1u << lane) - 1u));
        S.ckeys[half][pos] = key;
    }
    if (tl < V) S.rnk[half][tl] = 0;     // zero rank accumulators (tl covers V<=R<HT)
    bar_half(half);

    // ---- balanced enumeration (rank) sort: (key x part) work items ----
    if (V > 0) {
        int P = 1024 / V; if (P < 1) P = 1; if (P > 32) P = 32;
        int Vq = (V + P - 1) / P;
        int items = V * P;
        for (int it = tl; it < items; it += HT) {
            int p = it / P;
            int q = it - p * P;
            unsigned long long kp = S.ckeys[half][p];
            int jlo = q * Vq;
            int jhi = min(jlo + Vq, V);
            int rk = 0;
            #pragma unroll 4
            for (int j = jlo; j < jhi; j++)
                rk += (S.ckeys[half][j] < kp);
            if (rk) atomicAdd(&S.rnk[half][p], rk);
        }
    }
    bar_half(half);
    // scatter into sorted order
    if (tl < V) {
        unsigned long long kp = S.ckeys[half][tl];
        int rk = S.rnk[half][tl];
        int orig = (int)(kp & 0xFFFFFFFFu);
        float4 bb = S.box[half][orig];
        S.sb[half][rk] = bb;
        S.area[half][rk] = (bb.z - bb.x + 1.0f) * (bb.w - bb.y + 1.0f);
    }
    // pre-zero mask rows (peeling reads full rows, including below-diagonal words)
    for (int idx = tl; idx < V * RW; idx += HT)
        ((unsigned*)S.mask[half])[idx] = 0u;
    bar_half(half);

    // ---- publish sorted boxes (valid prefix) for cross-block selection ----
    if (tl < V)
        __stcg(&g_sb[(size_t)(b * NC + cc) * R + tl], S.sb[half][tl]);

    // ---- suppression bitmask, paired rows per warp; predicate-free lanes ----
    //   iou > T  <=>  (1+T)*inter - T*(ai+aj) > 0 (reals). When |diff| is larger
    //   than 1e-5 * union (>> combined rounding), the fast form is exact;
    //   otherwise evaluate the reference's literal (inter/union) > T.
    //   j>i / j<V corrections are applied by lane 0 to the ballot word.
    {
        const unsigned tailm = (V & 31) ? ((1u << (V & 31)) - 1u) : ~0u;
        for (int i = wl; i < V; i += 2 * NW) {
            const int i2 = i + NW;
            const bool has2 = (i2 < V);
            const int iw0 = i >> 5;
            const int iw2 = i2 >> 5;
            const unsigned am1 = ~((2u << (i & 31)) - 1u);    // bits j>i in word iw0
            const unsigned am2 = ~((2u << (i2 & 31)) - 1u);   // bits j>i2 in word iw2
            float4 bi  = S.sb[half][i];
            float  ai  = S.area[half][i];
            float4 bi2 = S.sb[half][has2 ? i2 : i];
            float  ai2 = S.area[half][has2 ? i2 : i];
            for (int jw = iw0; jw < VW; jw++) {
                int j  = (jw << 5) + lane;
                int jc = min(j, V - 1);
                float4 bj = S.sb[half][jc];
                float  aj = S.area[half][jc];

                bool sup1, sup2;
                {
                    float ix1 = fmaxf(bi.x, bj.x);
                    float iy1 = fmaxf(bi.y, bj.y);
                    float ix2 = fminf(bi.z, bj.z);
                    float iy2 = fminf(bi.w, bj.w);
                    float iw = fmaxf(ix2 - ix1 + 1.0f, 0.0f);
                    float ih = fmaxf(iy2 - iy1 + 1.0f, 0.0f);
                    float inter = iw * ih;
                    float asum = ai + aj;
                    float diff = fmaf(inter, 1.0f + NMS_T, -NMS_T * asum);
                    sup1 = diff > 0.0f;
                    float un = asum - inter;
                    if (fabsf(diff) <= 1e-5f * un)
                        sup1 = (inter / un) > NMS_T;   // rare exact fallback
                }
                {
                    float ix1 = fmaxf(bi2.x, bj.x);
                    float iy1 = fmaxf(bi2.y, bj.y);
                    float ix2 = fminf(bi2.z, bj.z);
                    float iy2 = fminf(bi2.w, bj.w);
                    float iw = fmaxf(ix2 - ix1 + 1.0f, 0.0f);
                    float ih = fmaxf(iy2 - iy1 + 1.0f, 0.0f);
                    float inter = iw * ih;
                    float asum = ai2 + aj;
                    float diff = fmaf(inter, 1.0f + NMS_T, -NMS_T * asum);
                    sup2 = diff > 0.0f;
                    float un = asum - inter;
                    if (fabsf(diff) <= 1e-5f * un)
                        sup2 = (inter / un) > NMS_T;   // rare exact fallback
                }
                unsigned bits1 = __ballot_sync(0xffffffffu, sup1);
                unsigned bits2 = __ballot_sync(0xffffffffu, sup2);
                if (lane == 0) {
                    unsigned vm = (jw == VW - 1) ? tailm : ~0u;
                    unsigned m1 = (jw == iw0) ? (vm & am1) : vm;
                    S.mask[half][i][jw] = bits1 & m1;
                    if (has2) {
                        unsigned m2 = (jw < iw2) ? 0u
                                     : ((jw == iw2) ? (vm & am2) : vm);
                        S.mask[half][i2][jw] = bits2 & m2;
                    }
                }
            }
        }
    }

    // ---- init peeling state ----
    if (tl < RW) {
        int lo = tl << 5, hi = min(V, lo + 32);
        unsigned lv = 0;
        if (hi > lo) lv = (hi - lo == 32) ? 0xffffffffu : ((1u << (hi - lo)) - 1u);
        S.slive[half][tl] = lv;
        S.skept[half][tl] = 0u;
    }
    bar_half(half);   // orders slive/skept/mask writes for this half

    // ---- exact parallel peeling NMS: independent per half, 2 barriers/round ----
    int alive = (V > 0);
    while (alive) {
        unsigned acc = 0;
        if (wl < RW) {
            for (int i = lane; i < V; i += 32)
                if ((S.slive[half][i >> 5] >> (i & 31)) & 1u) acc |= S.mask[half][i][wl];
            #pragma unroll
            for (int off = 16; off > 0; off >>= 1)
                acc |= __shfl_down_sync(0xffffffffu, acc, off);
            if (lane == 0) {
                unsigned kn = S.slive[half][wl] & ~acc;
                S.sknew[half][wl] = kn;
                S.skept[half][wl] |= kn;
            }
        }
        bar_half(half);                    // sknew visible; slive still old
        unsigned acc2 = 0;
        if (wl < RW) {
            for (int i = lane; i < V; i += 32)
                if ((S.sknew[half][i >> 5] >> (i & 31)) & 1u) acc2 |= S.mask[half][i][wl];
            #pragma unroll
            for (int off = 16; off > 0; off >>= 1)
                acc2 |= __shfl_down_sync(0xffffffffu, acc2, off);
            if (lane == 0)
                S.slive[half][wl] = S.slive[half][wl] & acc & ~acc2;  // acc in reg
        }
        bar_half(half);                    // updated slive visible
        unsigned any = 0;
        #pragma unroll
        for (int w2 = 0; w2 < RW; w2++) any |= S.slive[half][w2];
        alive = (any != 0u);               // uniform within the half
    }
    if (tl < RW)
        __stcg(&g_keep[(b * NC + cc) * RW + tl], S.skept[half][tl]);

    // ---- release writes, arrive; 20th-arriving half does selection ----
    __threadfence();
    bar_half(half);
    if (tl == 0) {
        S.sOld[half] = atomicAdd(&g_ctr[b], 1);
        __threadfence();
    }
    bar_half(half);

    if (S.sOld[half] == NC - 1 && tl < 32) {
        int cls = lane;     // 0..19 valid
        int cnt = 0;
        if (cls < NC) {
            #pragma unroll
            for (int w = 0; w < RW; w++) {
                unsigned kwv = __ldcg(&g_keep[(b * NC + cls) * RW + w]);
                S.skw[cls][w] = kwv;
                cnt += __popc(kwv);
            }
        }
        // warp inclusive scan of counts
        int incl = cnt;
        #pragma unroll
        for (int off = 1; off < 32; off <<= 1) {
            int n = __shfl_up_sync(0xffffffffu, incl, off);
            if (lane >= off) incl += n;
        }
        int total = __shfl_sync(0xffffffffu, incl, 31);
        S.sexcl[lane] = incl - cnt;
        __syncwarp();

        // zero this image's [K,5] slab
        for (int i = lane; i < KPAD * 5; i += 32)
            out[b * (KPAD * 5) + i] = 0.0f;
        __syncwarp();

        // slot-parallel emit: lane s owns output slot s
        int s = lane;
        int lim = min(total, KPAD);
        if (s < lim) {
            int cl = 0;
            #pragma unroll
            for (int c2 = 1; c2 < NC; c2++)
                if (S.sexcl[c2] <= s) cl = c2;
            int q = s - S.sexcl[cl];
            int w = 0;
            #pragma unroll
            for (int ww = 0; ww < RW; ww++) {
                int pc = __popc(S.skw[cl][ww]);
                bool here = (q < pc);
                if (!here) q -= pc;
                if (here) { w = ww; break; }
            }
            unsigned word = S.skw[cl][w];
            #pragma unroll
            for (int k = 0; k < 31; k++)
                if (k < q) word &= word - 1u;
            int bit = __ffs(word) - 1;
            float4 bb = __ldcg(&g_sb[(size_t)(b * NC + cl) * R + (w << 5) + bit]);
            float* o = out + b * (KPAD * 5) + s * 5;
            o[0] = bb.x; o[1] = bb.y; o[2] = bb.z; o[3] = bb.w;
            o[4] = (float)(cl + 1);
        }
        if (lane == 0) {
            int nbase = BATCH * KPAD * 5;
            if (out_size >= nbase + BATCH)
                out[nbase + b] = (float)lim;
            g_ctr[b] = 0;   // self-reset for next graph replay
        }
    }
}

extern "C" void kernel_launch(void* const* d_in, const int* in_sizes, int n_in,
                              void* d_out, int out_size)
{
    (void)in_sizes; (void)n_in;
    const float* cls_prob  = (const float*)d_in[0];
    const float* rois      = (const float*)d_in[1];
    const float* bbox_pred = (const float*)d_in[2];
    const float* im_info   = (const float*)d_in[3];
    const float* thr       = (const float*)d_in[4];

    // raise dynamic smem cap (idempotent host call, capture-safe)
    cudaFuncSetAttribute(fused_nms_kernel,
                         cudaFuncAttributeMaxDynamicSharedMemorySize,
                         (int)sizeof(Smem));

    fused_nms_kernel<<<BATCH * NPAIR, NT, sizeof(Smem)>>>(
        cls_prob, rois, bbox_pred, im_info, thr, (float*)d_out, out_size);
}

// round 12
// speedup vs baseline: 1.1559x; 1.1559x over previous
#include <cuda_runtime.h>
#include <math.h>

// Problem constants (shapes fixed by the dataset)
#define BATCH 8
#define R 300
#define C 21
#define NC 20           // foreground classes
#define KPAD 21         // output pad size == num_classes
#define RW 10           // ceil(300/32) keep-bitmask words
#define NMS_T 0.3f
#define NT 1024         // threads per block (2 independent halves of 512)
#define HT 512          // threads per half
#define NW 16           // warps per half
#define NPAIR (NC / 2)  // class pairs per image = blocks per image

// Cross-block intermediates (allocation-free rule: device globals)
__device__ float4   g_sb[BATCH * NC * R];      // sorted+clipped boxes per (b,class)
__device__ unsigned g_keep[BATCH * NC * RW];   // keep bitmask per (b,class)
__device__ int      g_ctr[BATCH];              // arrival counters (self-resetting)

struct Smem {
    float4  box[2][R];             // decoded boxes by original index
    float4  sb[2][R];              // boxes in sorted order (valid prefix)
    unsigned long long ckeys[2][R];// compacted valid keys (unordered; set only)
    float   area[2][R];            // areas in sorted order
    unsigned mask[2][R][RW];       // suppression bitmask (valid prefix)
    int sV[2];
    int sOld[2];
    unsigned slive[2][RW], skept[2][RW], sknew[2][RW];
    unsigned skw[NC][RW];          // tail selection scratch
    int sexcl[32];
};

// Per-half barrier: ids 1 and 2 (0 is reserved for __syncthreads).
__device__ __forceinline__ void bar_half(int half) {
    asm volatile("bar.sync %0, %1;" :: "r"(half + 1), "r"(HT) : "memory");
}

__global__ __launch_bounds__(NT, 1) void fused_nms_kernel(
    const float* __restrict__ cls_prob,   // [B,R,C]
    const float* __restrict__ rois,       // [B,R,5]
    const float* __restrict__ bbox_pred,  // [B,R,4C]
    const float* __restrict__ im_info,    // [B,3]
    const float* __restrict__ thr_arr,    // [C]
    float* __restrict__ out, int out_size)
{
    extern __shared__ __align__(16) unsigned char smem_raw[];
    Smem& S = *reinterpret_cast<Smem*>(smem_raw);

    const int blk  = blockIdx.x;
    const int b    = blk / NPAIR;
    const int t    = threadIdx.x;
    const int half = t >> 9;                 // 0 or 1: which class of the pair
    const int tl   = t & (HT - 1);           // thread id within half
    const int lane = t & 31;
    const int wl   = tl >> 5;                // warp id within half (0..15)
    const int cc   = (blk % NPAIR) * 2 + half;   // 0..19
    const int c    = cc + 1;                 // class id 1..20

    if (tl == 0) S.sV[half] = 0;             // ordered before use by bar_half below

    const float thr = thr_arr[c];
    const float H1 = im_info[b * 3 + 0] - 1.0f;
    const float W1 = im_info[b * 3 + 1] - 1.0f;

    // ---- decode + clip + key (one row per thread; arithmetic identical to R1) ----
    int valid = 0;
    unsigned long long key = ~0ULL;
    const int r = tl;
    if (r < R) {
        const float* rp = rois + (size_t)(b * R + r) * 5;
        float x1 = rp[1], y1 = rp[2], x2 = rp[3], y2 = rp[4];
        float w  = x2 - x1 + 1.0f;
        float h  = y2 - y1 + 1.0f;
        float cx = x1 + 0.5f * w;
        float cy = y1 + 0.5f * h;

        // 16B-aligned: byte offset = 336*(b*R+r) + 16*c
        const float4 d4 = *reinterpret_cast<const float4*>(
            bbox_pred + (size_t)(b * R + r) * (4 * C) + 4 * c);
        float d0 = d4.x * 0.1f;
        float d1 = d4.y * 0.1f;
        float d2 = d4.z * 0.2f;
        float d3 = d4.w * 0.2f;

        float pcx = d0 * w + cx;
        float pcy = d1 * h + cy;
        float pw  = expf(d2) * w;
        float ph  = expf(d3) * h;

        float bx1 = fminf(fmaxf(pcx - 0.5f * pw, 0.0f), W1);
        float by1 = fminf(fmaxf(pcy - 0.5f * ph, 0.0f), H1);
        float bx2 = fminf(fmaxf(pcx + 0.5f * pw, 0.0f), W1);
        float by2 = fminf(fmaxf(pcy + 0.5f * ph, 0.0f), H1);
        S.box[half][r] = make_float4(bx1, by1, bx2, by2);

        float s = cls_prob[(size_t)(b * R + r) * C + c];
        valid = (s > thr) ? 1 : 0;

        // monotone float->uint, inverted => ascending sort == descending score,
        // low 32 bits = original index (stable tie-break).
        unsigned u = __float_as_uint(s);
        unsigned m = (u & 0x80000000u) ? ~u : (u | 0x80000000u);
        key = (((unsigned long long)(~m)) << 32) | (unsigned)r;
    }
    bar_half(half);    // sV init visible before atomics below

    // ---- UNSTABLE compaction of valid keys (order-free: the rank sort is a
    //      pure key-set operation; keys are unique so ranks are a permutation) ----
    unsigned bal = __ballot_sync(0xffffffffu, valid);
    {
        int cntw = __popc(bal);
        int base = 0;
        if (lane == 0 && cntw) base = atomicAdd(&S.sV[half], cntw);
        base = __shfl_sync(0xffffffffu, base, 0);
        if (valid) {
            int pos = base + __popc(bal & ((1u << lane) - 1u));
            S.ckeys[half][pos] = key;
        }
    }
    bar_half(half);
    const int V  = S.sV[half];
    const int VW = (V + 31) >> 5;

    // ---- enumeration (rank) sort over the V compacted keys (per half) ----
    if (V > 0) {
        if (V <= 256) {
            // 2 threads per key: even counts [0,Vh), odd counts [Vh,V)
            int p = tl >> 1;
            int pc = (p < V) ? p : (V - 1);
            unsigned long long kp = S.ckeys[half][pc];
            int hh = tl & 1;
            int Vh = (V + 1) >> 1;
            int jlo = hh ? Vh : 0;
            int jhi = hh ? V : Vh;
            int rk = 0;
            #pragma unroll 4
            for (int j = jlo; j < jhi; j++)
                rk += (S.ckeys[half][j] < kp);
            rk += __shfl_xor_sync(0xffffffffu, rk, 1);
            if (hh == 0 && p < V) {
                int orig = (int)(kp & 0xFFFFFFFFu);
                float4 bb = S.box[half][orig];
                S.sb[half][rk] = bb;
                S.area[half][rk] = (bb.z - bb.x + 1.0f) * (bb.w - bb.y + 1.0f);
            }
        } else {
            if (tl < V) {
                unsigned long long kp = S.ckeys[half][tl];
                int rk = 0;
                #pragma unroll 4
                for (int j = 0; j < V; j++)
                    rk += (S.ckeys[half][j] < kp);
                int orig = (int)(kp & 0xFFFFFFFFu);
                float4 bb = S.box[half][orig];
                S.sb[half][rk] = bb;
                S.area[half][rk] = (bb.z - bb.x + 1.0f) * (bb.w - bb.y + 1.0f);
            }
        }
    }
    // pre-zero mask rows (peeling reads full rows, including below-diagonal words)
    for (int idx = tl; idx < V * RW; idx += HT)
        ((unsigned*)S.mask[half])[idx] = 0u;
    bar_half(half);

    // ---- publish sorted boxes (valid prefix) for cross-block selection ----
    if (tl < V)
        __stcg(&g_sb[(size_t)(b * NC + cc) * R + tl], S.sb[half][tl]);

    // ---- suppression bitmask, paired rows per warp; predicate-free lanes ----
    //   iou > T  <=>  (1+T)*inter - T*(ai+aj) > 0 (reals). When |diff| is larger
    //   than 1e-5 * union (>> combined rounding), the fast form is exact;
    //   otherwise evaluate the reference's literal (inter/union) > T.
    //   j>i / j<V corrections are applied by lane 0 to the ballot word.
    {
        const unsigned tailm = (V & 31) ? ((1u << (V & 31)) - 1u) : ~0u;
        for (int i = wl; i < V; i += 2 * NW) {
            const int i2 = i + NW;
            const bool has2 = (i2 < V);
            const int iw0 = i >> 5;
            const int iw2 = i2 >> 5;
            const unsigned am1 = ~((2u << (i & 31)) - 1u);    // bits j>i in word iw0
            const unsigned am2 = ~((2u << (i2 & 31)) - 1u);   // bits j>i2 in word iw2
            float4 bi  = S.sb[half][i];
            float  ai  = S.area[half][i];
            float4 bi2 = S.sb[half][has2 ? i2 : i];
            float  ai2 = S.area[half][has2 ? i2 : i];
            for (int jw = iw0; jw < VW; jw++) {
                int j  = (jw << 5) + lane;
                int jc = min(j, V - 1);
                float4 bj = S.sb[half][jc];
                float  aj = S.area[half][jc];

                bool sup1, sup2;
                {
                    float ix1 = fmaxf(bi.x, bj.x);
                    float iy1 = fmaxf(bi.y, bj.y);
                    float ix2 = fminf(bi.z, bj.z);
                    float iy2 = fminf(bi.w, bj.w);
                    float iw = fmaxf(ix2 - ix1 + 1.0f, 0.0f);
                    float ih = fmaxf(iy2 - iy1 + 1.0f, 0.0f);
                    float inter = iw * ih;
                    float asum = ai + aj;
                    float diff = fmaf(inter, 1.0f + NMS_T, -NMS_T * asum);
                    sup1 = diff > 0.0f;
                    float un = asum - inter;
                    if (fabsf(diff) <= 1e-5f * un)
                        sup1 = (inter / un) > NMS_T;   // rare exact fallback
                }
                {
                    float ix1 = fmaxf(bi2.x, bj.x);
                    float iy1 = fmaxf(bi2.y, bj.y);
                    float ix2 = fminf(bi2.z, bj.z);
                    float iy2 = fminf(bi2.w, bj.w);
                    float iw = fmaxf(ix2 - ix1 + 1.0f, 0.0f);
                    float ih = fmaxf(iy2 - iy1 + 1.0f, 0.0f);
                    float inter = iw * ih;
                    float asum = ai2 + aj;
                    float diff = fmaf(inter, 1.0f + NMS_T, -NMS_T * asum);
                    sup2 = diff > 0.0f;
                    float un = asum - inter;
                    if (fabsf(diff) <= 1e-5f * un)
                        sup2 = (inter / un) > NMS_T;   // rare exact fallback
                }
                unsigned bits1 = __ballot_sync(0xffffffffu, sup1);
                unsigned bits2 = __ballot_sync(0xffffffffu, sup2);
                if (lane == 0) {
                    unsigned vm = (jw == VW - 1) ? tailm : ~0u;
                    unsigned m1 = (jw == iw0) ? (vm & am1) : vm;
                    S.mask[half][i][jw] = bits1 & m1;
                    if (has2) {
                        unsigned m2 = (jw < iw2) ? 0u
                                     : ((jw == iw2) ? (vm & am2) : vm);
                        S.mask[half][i2][jw] = bits2 & m2;
                    }
                }
            }
        }
    }

    // ---- init peeling state ----
    if (tl < RW) {
        int lo = tl << 5, hi = min(V, lo + 32);
        unsigned lv = 0;
        if (hi > lo) lv = (hi - lo == 32) ? 0xffffffffu : ((1u << (hi - lo)) - 1u);
        S.slive[half][tl] = lv;
        S.skept[half][tl] = 0u;
    }
    bar_half(half);   // orders slive/skept/mask writes for this half

    // ---- exact parallel peeling NMS: independent per half, 2 barriers/round ----
    int alive = (V > 0);
    while (alive) {
        unsigned acc = 0;
        if (wl < RW) {
            for (int i = lane; i < V; i += 32)
                if ((S.slive[half][i >> 5] >> (i & 31)) & 1u) acc |= S.mask[half][i][wl];
            #pragma unroll
            for (int off = 16; off > 0; off >>= 1)
                acc |= __shfl_down_sync(0xffffffffu, acc, off);
            if (lane == 0) {
                unsigned kn = S.slive[half][wl] & ~acc;
                S.sknew[half][wl] = kn;
                S.skept[half][wl] |= kn;
            }
        }
        bar_half(half);                    // sknew visible; slive still old
        unsigned acc2 = 0;
        if (wl < RW) {
            for (int i = lane; i < V; i += 32)
                if ((S.sknew[half][i >> 5] >> (i & 31)) & 1u) acc2 |= S.mask[half][i][wl];
            #pragma unroll
            for (int off = 16; off > 0; off >>= 1)
                acc2 |= __shfl_down_sync(0xffffffffu, acc2, off);
            if (lane == 0)
                S.slive[half][wl] = S.slive[half][wl] & acc & ~acc2;  // acc in reg
        }
        bar_half(half);                    // updated slive visible
        unsigned any = 0;
        #pragma unroll
        for (int w2 = 0; w2 < RW; w2++) any |= S.slive[half][w2];
        alive = (any != 0u);               // uniform within the half
    }
    if (tl < RW)
        __stcg(&g_keep[(b * NC + cc) * RW + tl], S.skept[half][tl]);

    // ---- release writes, arrive; 20th-arriving half does selection ----
    __threadfence();
    bar_half(half);
    if (tl == 0) {
        S.sOld[half] = atomicAdd(&g_ctr[b], 1);
        __threadfence();
    }
    bar_half(half);

    if (S.sOld[half] == NC - 1 && tl < 32) {
        int cls = lane;     // 0..19 valid
        int cnt = 0;
        if (cls < NC) {
            #pragma unroll
            for (int w = 0; w < RW; w++) {
                unsigned kwv = __ldcg(&g_keep[(b * NC + cls) * RW + w]);
                S.skw[cls][w] = kwv;
                cnt += __popc(kwv);
            }
        }
        // warp inclusive scan of counts
        int incl = cnt;
        #pragma unroll
        for (int off = 1; off < 32; off <<= 1) {
            int n = __shfl_up_sync(0xffffffffu, incl, off);
            if (lane >= off) incl += n;
        }
        int total = __shfl_sync(0xffffffffu, incl, 31);
        S.sexcl[lane] = incl - cnt;
        __syncwarp();

        // zero this image's [K,5] slab
        for (int i = lane; i < KPAD * 5; i += 32)
            out[b * (KPAD * 5) + i] = 0.0f;
        __syncwarp();

        // slot-parallel emit: lane s owns output slot s
        int s = lane;
        int lim = min(total, KPAD);
        if (s < lim) {
            int cl = 0;
            #pragma unroll
            for (int c2 = 1; c2 < NC; c2++)
                if (S.sexcl[c2] <= s) cl = c2;
            int q = s - S.sexcl[cl];
            int w = 0;
            #pragma unroll
            for (int ww = 0; ww < RW; ww++) {
                int pc = __popc(S.skw[cl][ww]);
                bool here = (q < pc);
                if (!here) q -= pc;
                if (here) { w = ww; break; }
            }
            unsigned word = S.skw[cl][w];
            #pragma unroll
            for (int k = 0; k < 31; k++)
                if (k < q) word &= word - 1u;
            int bit = __ffs(word) - 1;
            float4 bb = __ldcg(&g_sb[(size_t)(b * NC + cl) * R + (w << 5) + bit]);
            float* o = out + b * (KPAD * 5) + s * 5;
            o[0] = bb.x; o[1] = bb.y; o[2] = bb.z; o[3] = bb.w;
            o[4] = (float)(cl + 1);
        }
        if (lane == 0) {
            int nbase = BATCH * KPAD * 5;
            if (out_size >= nbase + BATCH)
                out[nbase + b] = (float)lim;
            g_ctr[b] = 0;   // self-reset for next graph replay
        }
    }
}

extern "C" void kernel_launch(void* const* d_in, const int* in_sizes, int n_in,
                              void* d_out, int out_size)
{
    (void)in_sizes; (void)n_in;
    const float* cls_prob  = (const float*)d_in[0];
    const float* rois      = (const float*)d_in[1];
    const float* bbox_pred = (const float*)d_in[2];
    const float* im_info   = (const float*)d_in[3];
    const float* thr       = (const float*)d_in[4];

    // raise dynamic smem cap (idempotent host call, capture-safe)
    cudaFuncSetAttribute(fused_nms_kernel,
                         cudaFuncAttributeMaxDynamicSharedMemorySize,
                         (int)sizeof(Smem));

    fused_nms_kernel<<<BATCH * NPAIR, NT, sizeof(Smem)>>>(
        cls_prob, rois, bbox_pred, im_info, thr, (float*)d_out, out_size);
}